// round 7
// baseline (speedup 1.0000x reference)
#include <cuda_runtime.h>
#include <math.h>

#define EDGES 65536
#define GRID  2048
#define EPB   (EDGES / GRID)   // 32 edges per block (phase-2)
#define W3J_TOTAL 1875
#define NZ_MAX (1875 + 99)     // + dummy entries for empty slots
#define ZSTRIDE 104
#define OUT_ALL_OFF ((size_t)EDGES * 9 * 128)   // 75497472

#define ZP_WARPS 8
#define ZP_EPW   8
#define ZP_GRID  (EDGES / (ZP_WARPS * ZP_EPW))  // 1024

// ---- key tables ----
__constant__ int KEY_LA[23]  = {0,1,2,3, 0,1,1,2,2,3, 0,1,1,2,2,3,3, 0,1,2,2,3,3};
__constant__ int KEY_LB[23]  = {0,1,2,3, 1,0,2,1,3,2, 2,1,3,0,2,1,3, 3,2,1,3,0,2};
__constant__ int KEY_LO[23]  = {0,0,0,0, 1,1,1,1,1,1, 2,2,2,2,2,2,2, 3,3,3,3,3,3};
__constant__ int W3J_OFF[23] = {0,1,10,35, 84,93,102,147,192,297,
                                402,427,472,577,602,727,832,
                                1077,1126,1231,1336,1581,1630};

__constant__ float c_factf[11]  = {1.f,1.f,2.f,6.f,24.f,120.f,720.f,5040.f,40320.f,362880.f,3628800.f};
__constant__ float c_rfactf[11] = {1.0f, 1.0f, 0.5f, 1.0f/6.0f, 1.0f/24.0f, 1.0f/120.0f, 1.0f/720.0f,
                                   1.0f/5040.0f, 1.0f/40320.0f, 1.0f/362880.0f, 1.0f/3628800.0f};

__device__ float g_w3j[W3J_TOTAL];
__device__ float2 g_nz[NZ_MAX];        // per-slot entries (coeff, pidx)
__device__ float2 g_lane_nz[NZ_MAX];   // per-lane streams (coeff, meta)
__device__ int g_lane_off[33];
__device__ int g_total;                // total stream entries
__device__ float g_z[(size_t)EDGES * ZSTRIDE];   // 27.3 MB intermediate

// ================= init: fp32 Wigner-3j tensors =================
struct F2 { float re, im; };
__device__ __forceinline__ F2 cmul(F2 a, F2 b) {
    return F2{a.re * b.re - a.im * b.im, a.re * b.im + a.im * b.re};
}
__device__ __forceinline__ F2 cconj(F2 a) { return F2{a.re, -a.im}; }
__device__ __forceinline__ F2 cscale(F2 a, float s) { return F2{a.re * s, a.im * s}; }

__device__ float su2_cg(int j1, int m1, int j2, int m2, int j3, int m3) {
    if (m3 != m1 + m2) return 0.0f;
    float pref = sqrtf((2.0f * j3 + 1.0f) * c_factf[j3 + j1 - j2] * c_factf[j3 - j1 + j2] *
                       c_factf[j1 + j2 - j3] * c_rfactf[j1 + j2 + j3 + 1]);
    pref *= sqrtf(c_factf[j3 + m3] * c_factf[j3 - m3] * c_factf[j1 - m1] * c_factf[j1 + m1] *
                  c_factf[j2 - m2] * c_factf[j2 + m2]);
    int kmin = max(0, max(j2 - j3 - m1, j1 - j3 + m2));
    int kmax = min(j1 + j2 - j3, min(j1 - m1, j2 + m2));
    float s = 0.0f;
    for (int k = kmin; k <= kmax; k++) {
        float term = c_rfactf[k] * c_rfactf[j1 + j2 - j3 - k] * c_rfactf[j1 - m1 - k] *
                     c_rfactf[j2 + m2 - k] * c_rfactf[j3 - j2 + m1 + k] * c_rfactf[j3 - j1 - m2 + k];
        s += (k & 1) ? -term : term;
    }
    return pref * s;
}

__device__ __forceinline__ F2 negi_pow(int l) {
    switch (l & 3) {
        case 0: return F2{1.0f, 0.0f};
        case 1: return F2{0.0f, -1.0f};
        case 2: return F2{-1.0f, 0.0f};
        default: return F2{0.0f, 1.0f};
    }
}

__device__ int q_col_entries(int l, int c, int* rows, F2* vals) {
    F2 pref = negi_pow(l);
    const float s = 0.70710678f;
    int mu = c - l;
    if (mu == 0) { rows[0] = l; vals[0] = pref; return 1; }
    if (mu > 0) {
        rows[0] = l - mu; vals[0] = cscale(pref, s);
        float sgn = (mu & 1) ? -1.0f : 1.0f;
        rows[1] = l + mu; vals[1] = cscale(pref, sgn * s);
        return 2;
    }
    int a = -mu;
    rows[0] = l - a; vals[0] = cmul(pref, F2{0.0f, -s});
    float sgn = (a & 1) ? -1.0f : 1.0f;
    rows[1] = l + a; vals[1] = cmul(pref, F2{0.0f, sgn * s});
    return 2;
}

__device__ int q_row_entries(int l, int r, int* cols, F2* vals) {
    F2 pref = negi_pow(l);
    const float s = 0.70710678f;
    int mu = r - l;
    if (mu == 0) { cols[0] = l; vals[0] = pref; return 1; }
    if (mu < 0) {
        int a = -mu;
        cols[0] = l + a; vals[0] = cscale(pref, s);
        cols[1] = l - a; vals[1] = cmul(pref, F2{0.0f, -s});
        return 2;
    }
    float sgn = (mu & 1) ? -1.0f : 1.0f;
    cols[0] = l + mu; vals[0] = cscale(pref, sgn * s);
    cols[1] = l - mu; vals[1] = cmul(pref, F2{0.0f, sgn * s});
    return 2;
}

__global__ void w3j_init_kernel() {
    __shared__ float sC[343];
    __shared__ float sCr[245];
    __shared__ float sred[256];
    int key = blockIdx.x;
    int la = KEY_LA[key], lb = KEY_LB[key], lo = KEY_LO[key];
    int na = 2 * la + 1, nb = 2 * lb + 1, no = 2 * lo + 1;
    int n = na * nb * no;
    int t = threadIdx.x;

    for (int idx = t; idx < n; idx += blockDim.x) {
        int i = idx / (nb * no);
        int rem = idx % (nb * no);
        int k = rem / no;
        int m = rem % no;
        int m1 = i - la, m2 = k - lb, m3 = m - lo;
        sC[idx] = (m3 == m1 + m2) ? su2_cg(la, m1, lb, m2, lo, m3) : 0.0f;
    }
    __syncthreads();

    float local_sq = 0.0f;
    for (int idx = t; idx < n; idx += blockDim.x) {
        int ja = idx / (nb * no);
        int rem = idx % (nb * no);
        int jb = rem / no;
        int jn = rem % no;
        int r1[2]; F2 v1[2]; int n1 = q_col_entries(la, ja, r1, v1);
        int r2[2]; F2 v2[2]; int n2 = q_col_entries(lb, jb, r2, v2);
        int c3[2]; F2 v3[2]; int n3 = q_row_entries(lo, jn, c3, v3);
        F2 acc{0.0f, 0.0f};
        for (int a = 0; a < n1; a++)
            for (int b = 0; b < n2; b++)
                for (int c = 0; c < n3; c++) {
                    F2 q = cmul(cmul(v1[a], v2[b]), cconj(v3[c]));
                    float cv = sC[(r1[a] * nb + r2[b]) * no + c3[c]];
                    acc.re += q.re * cv;
                    acc.im += q.im * cv;
                }
        sCr[idx] = acc.re;
        local_sq += acc.re * acc.re;
    }
    sred[t] = local_sq;
    __syncthreads();
    for (int s = 128; s > 0; s >>= 1) {
        if (t < s) sred[t] += sred[t + s];
        __syncthreads();
    }
    float inv = rsqrtf(sred[0]);
    for (int idx = t; idx < n; idx += blockDim.x)
        g_w3j[W3J_OFF[key] + idx] = sCr[idx] * inv;
}

// slot (0..98) -> (key, k-within-output)
__device__ __forceinline__ void slot_decode(int t, int& key, int& k) {
    if (t < 4) { key = t; k = 0; }
    else if (t < 22) { int q = t - 4; key = 4 + q / 3; k = q % 3; }
    else if (t < 57) { int q = t - 22; key = 10 + q / 5; k = q % 5; }
    else { int q = t - 57; key = 17 + q / 7; k = q % 7; }
}

// slot -> index within padded z row
__device__ __forceinline__ int zmap(int slot) {
    return slot + (slot >= 22 ? 2 : 0) + (slot >= 57 ? 1 : 0);
}

// ========== compress: per-slot nz lists -> load-balanced 32-lane streams ==========
// meta layout: bits 0-7 pidx, bits 8-14 dst, bit 15 end-of-slot
__global__ void w3j_compress_kernel() {
    __shared__ int scnt[99];
    __shared__ int soff[99];
    __shared__ int srank[99];
    __shared__ int slane[99];
    __shared__ int sdest[99];
    __shared__ int lstart[33];
    int t = threadIdx.x;
    int key = 0, k = 0;
    bool valid = (t < 99);
    if (valid) slot_decode(t, key, k);
    int la = KEY_LA[key], lb = KEY_LB[key], lo = KEY_LO[key];
    int na = 2 * la + 1, nb = 2 * lb + 1, no = 2 * lo + 1;
    int woff = W3J_OFF[key];
    int cnt = 0;
    if (valid) {
        for (int i = 0; i < na; i++)
            for (int j = 0; j < nb; j++)
                if (fabsf(g_w3j[woff + (i * nb + j) * no + k]) > 1e-10f) cnt++;
        if (cnt == 0) cnt = 1;   // dummy entry so z[dst] still gets written
        scnt[t] = cnt;
    }
    __syncthreads();
    if (t == 0) {
        int acc = 0;
        for (int i = 0; i < 99; i++) { soff[i] = acc; acc += scnt[i]; }
    }
    __syncthreads();
    // write per-slot entries (plain pidx)
    if (valid) {
        int w = soff[t];
        int written = 0;
        for (int i = 0; i < na; i++)
            for (int j = 0; j < nb; j++) {
                float c = g_w3j[woff + (i * nb + j) * no + k];
                if (fabsf(c) > 1e-10f) {
                    int pidx = (la * la + i) * 16 + (lb * lb + j);
                    g_nz[w++] = make_float2(c, __int_as_float(pidx));
                    written++;
                }
            }
        if (written == 0)
            g_nz[w++] = make_float2(0.0f, __int_as_float(0));
    }
    __syncthreads();
    // rank by nnz desc (stable)
    if (valid) {
        int rank = 0;
        for (int j = 0; j < 99; j++)
            if (scnt[j] > cnt || (scnt[j] == cnt && j < t)) rank++;
        srank[t] = rank;
        // boustrophedon lane assignment
        int grp = rank >> 5, pos = rank & 31;
        slane[t] = (grp & 1) ? (31 - pos) : pos;
    }
    __syncthreads();
    // intra-lane offset: sum of cnts of slots in same lane with smaller rank
    if (valid) {
        int myLane = slane[t], myRank = srank[t];
        int intra = 0;
        for (int j = 0; j < 99; j++)
            if (slane[j] == myLane && srank[j] < myRank) intra += scnt[j];
        sdest[t] = intra;   // lane start added below
    }
    // lane totals + prefix
    __syncthreads();
    if (t < 32) {
        int load = 0;
        for (int j = 0; j < 99; j++)
            if (slane[j] == t) load += scnt[j];
        lstart[t + 1] = load;   // temp: per-lane totals shifted
    }
    __syncthreads();
    if (t == 0) {
        lstart[0] = 0;
        for (int l = 0; l < 32; l++) lstart[l + 1] += lstart[l];
        g_total = lstart[32];
        for (int l = 0; l <= 32; l++) g_lane_off[l] = lstart[l];
    }
    __syncthreads();
    // copy entries into lane streams with end flag + dst on last entry of slot
    if (valid) {
        int dst = zmap(t);
        int src = soff[t];
        int dbase = lstart[slane[t]] + sdest[t];
        for (int n = 0; n < cnt; n++) {
            float2 e = g_nz[src + n];
            int meta = __float_as_int(e.y) & 255;
            if (n == cnt - 1) meta |= (dst << 8) | (1 << 15);
            g_lane_nz[dbase + n] = make_float2(e.x, __int_as_float(meta));
        }
    }
}

// ================= z-pass: one warp per edge, barrier-free =================
__global__ void __launch_bounds__(ZP_WARPS * 32)
z_pass_kernel(const float* __restrict__ x, const float* __restrict__ y) {
    __shared__ float2 sstream[NZ_MAX];
    __shared__ float sProd[ZP_WARPS][256];
    int t = threadIdx.x;
    int w = t >> 5, lane = t & 31;
    int total = g_total;
    for (int i = t; i < total; i += ZP_WARPS * 32) sstream[i] = g_lane_nz[i];
    int lbeg = g_lane_off[lane], lend = g_lane_off[lane + 1];
    __syncthreads();

    int ebase = (blockIdx.x * ZP_WARPS + w) * ZP_EPW;
    float pre = (lane < 16) ? x[(size_t)ebase * 16 + lane]
                            : y[(size_t)ebase * 16 + (lane - 16)];
    for (int ei = 0; ei < ZP_EPW; ++ei) {
        int e = ebase + ei;
        float v = pre;
#pragma unroll
        for (int r = 0; r < 8; r++) {
            int p = r * 32 + lane;
            sProd[w][p] = __shfl_sync(0xffffffffu, v, p >> 4) *
                          __shfl_sync(0xffffffffu, v, 16 + (p & 15));
        }
        if (ei + 1 < ZP_EPW) {
            int en = e + 1;
            pre = (lane < 16) ? x[(size_t)en * 16 + lane]
                              : y[(size_t)en * 16 + (lane - 16)];
        }
        __syncwarp();
        float* zrow = g_z + (size_t)e * ZSTRIDE;
        float acc = 0.0f;
        for (int i = lbeg; i < lend; i++) {
            float2 ent = sstream[i];
            int meta = __float_as_int(ent.y);
            acc = fmaf(ent.x, sProd[w][meta & 255], acc);
            if (meta & (1 << 15)) {
                zrow[(meta >> 8) & 127] = acc;
                acc = 0.0f;
            }
        }
        __syncwarp();
    }
}

// ================= phase 2: pure streaming, barrier-free edge loop =================
__device__ __forceinline__ float fsig(float v) { return 1.0f / (1.0f + __expf(-v)); }

__global__ void __launch_bounds__(128, 6)
cg_main_kernel(const float* __restrict__ wcg, const float* __restrict__ bcg,
               const float* __restrict__ wall, const float* __restrict__ ball,
               float* __restrict__ out) {
    __shared__ float sWall[35];
    __shared__ float sBall[4];
    int t = threadIdx.x;
    if (t < 35) sWall[t] = wall[t];
    if (t < 4) sBall[t] = ball[t];
    __syncthreads();   // only barrier in this kernel

    // per-channel weights in registers
    float w00 = wcg[t], w01 = wcg[128 + t], w02 = wcg[256 + t], w03 = wcg[384 + t];
    float a0w = wcg[512 + t], a1w = wcg[768 + t], a2w = wcg[1024 + t], a3w = wcg[1280 + t];
    float c0w = wcg[640 + t], c1w = wcg[896 + t], c2w = wcg[1152 + t], c3w = wcg[1408 + t];
    float uw0 = wcg[1536 + t], uw1 = wcg[1664 + t], uw2 = wcg[1792 + t];
    float uw3 = wcg[1920 + t], uw4 = wcg[2048 + t], uw5 = wcg[2176 + t];
    float vw0 = wcg[2304 + t], vw1 = wcg[2432 + t], vw2 = wcg[2560 + t], vw3 = wcg[2688 + t];
    float vw4 = wcg[2816 + t], vw5 = wcg[2944 + t], vw6 = wcg[3072 + t];
    float b0 = bcg[t], b1 = bcg[128 + t], b2 = bcg[256 + t];

    int e0 = blockIdx.x * EPB;
    for (int ei = 0; ei < EPB; ++ei) {
        int e = e0 + ei;
        const float* Z = g_z + (size_t)e * ZSTRIDE;
        const float4* Zv = (const float4*)Z;

        float4 z0 = __ldg(Zv);
        float v0 = fmaf(z0.x, w00, fmaf(z0.y, w01, fmaf(z0.z, w02, z0.w * w03)));
        v0 = 0.5f * v0 + b0;
        float scv = v0 * fsig(v0);
        float g0 = fmaf(z0.x, a0w, fmaf(z0.y, a1w, fmaf(z0.z, a2w, z0.w * a3w)));
        g0 = fsig(0.5f * g0 + b1);
        float g1 = fmaf(z0.x, c0w, fmaf(z0.y, c1w, fmaf(z0.z, c2w, z0.w * c3w)));
        g1 = fsig(0.5f * g1 + b2);

        // entry 2 (lo=1): Z[4..21]
        float u0, u1, u2;
        {
            float4 v;
            v = __ldg(Zv + 1);
            u0 = v.x * uw0; u1 = v.y * uw0; u2 = v.z * uw0; u0 = fmaf(v.w, uw1, u0);
            v = __ldg(Zv + 2);
            u1 = fmaf(v.x, uw1, u1); u2 = fmaf(v.y, uw1, u2);
            u0 = fmaf(v.z, uw2, u0); u1 = fmaf(v.w, uw2, u1);
            v = __ldg(Zv + 3);
            u2 = fmaf(v.x, uw2, u2); u0 = fmaf(v.y, uw3, u0);
            u1 = fmaf(v.z, uw3, u1); u2 = fmaf(v.w, uw3, u2);
            v = __ldg(Zv + 4);
            u0 = fmaf(v.x, uw4, u0); u1 = fmaf(v.y, uw4, u1);
            u2 = fmaf(v.z, uw4, u2); u0 = fmaf(v.w, uw5, u0);
            float2 v2 = __ldg((const float2*)(Z + 20));
            u1 = fmaf(v2.x, uw5, u1); u2 = fmaf(v2.y, uw5, u2);
        }
        // entry 3 (lo=2): Z[24..58]
        float q0, q1, q2, q3, q4;
        {
            float4 v;
            v = __ldg(Zv + 6);
            q0 = v.x * vw0; q1 = v.y * vw0; q2 = v.z * vw0; q3 = v.w * vw0;
            v = __ldg(Zv + 7);
            q4 = v.x * vw0; q0 = fmaf(v.y, vw1, q0); q1 = fmaf(v.z, vw1, q1); q2 = fmaf(v.w, vw1, q2);
            v = __ldg(Zv + 8);
            q3 = fmaf(v.x, vw1, q3); q4 = fmaf(v.y, vw1, q4); q0 = fmaf(v.z, vw2, q0); q1 = fmaf(v.w, vw2, q1);
            v = __ldg(Zv + 9);
            q2 = fmaf(v.x, vw2, q2); q3 = fmaf(v.y, vw2, q3); q4 = fmaf(v.z, vw2, q4); q0 = fmaf(v.w, vw3, q0);
            v = __ldg(Zv + 10);
            q1 = fmaf(v.x, vw3, q1); q2 = fmaf(v.y, vw3, q2); q3 = fmaf(v.z, vw3, q3); q4 = fmaf(v.w, vw3, q4);
            v = __ldg(Zv + 11);
            q0 = fmaf(v.x, vw4, q0); q1 = fmaf(v.y, vw4, q1); q2 = fmaf(v.z, vw4, q2); q3 = fmaf(v.w, vw4, q3);
            v = __ldg(Zv + 12);
            q4 = fmaf(v.x, vw4, q4); q0 = fmaf(v.y, vw5, q0); q1 = fmaf(v.z, vw5, q1); q2 = fmaf(v.w, vw5, q2);
            v = __ldg(Zv + 13);
            q3 = fmaf(v.x, vw5, q3); q4 = fmaf(v.y, vw5, q4); q0 = fmaf(v.z, vw6, q0); q1 = fmaf(v.w, vw6, q1);
            v = __ldg(Zv + 14);   // Z[56..58]; Z[59] pad, unused
            q2 = fmaf(v.x, vw6, q2); q3 = fmaf(v.y, vw6, q3); q4 = fmaf(v.z, vw6, q4);
        }

        const float S1 = 0.70710678118654752f;   // sqrt(3/6)
        const float S2 = 0.84515425472851657f;   // sqrt(5/7)
        size_t base = ((size_t)e * 9) * 128 + t;
        out[base] = scv;
        float gg = S1 * g0;
        out[base + 128] = u0 * gg;
        out[base + 256] = u1 * gg;
        out[base + 384] = u2 * gg;
        float hh = S2 * g1;
        out[base + 512] = q0 * hh;
        out[base + 640] = q1 * hh;
        out[base + 768] = q2 * hh;
        out[base + 896] = q3 * hh;
        out[base + 1024] = q4 * hh;

        // ---- "all" branch: 16 outputs ----
        if (t < 16) {
            float* oa = out + OUT_ALL_OFF + (size_t)e * 16;
            if (t == 0) {
                float v = 0.5f * (z0.x * sWall[0] + z0.y * sWall[1] + z0.z * sWall[2] + z0.w * sWall[3]) + sBall[0];
                oa[0] = v * fsig(v);
            } else if (t < 4) {
                int k = t - 1;
                float g = fsig(0.5f * (z0.x * sWall[4] + z0.y * sWall[7] + z0.z * sWall[10] + z0.w * sWall[13]) + sBall[1]);
                float u = 0.f;
#pragma unroll
                for (int p = 0; p < 6; p++) u += __ldg(Z + 4 + 3 * p + k) * sWall[16 + p];
                oa[t] = 0.70710678118654752f * u * g;
            } else if (t < 9) {
                int k = t - 4;
                float g = fsig(0.5f * (z0.x * sWall[5] + z0.y * sWall[8] + z0.z * sWall[11] + z0.w * sWall[14]) + sBall[2]);
                float u = 0.f;
#pragma unroll
                for (int p = 0; p < 7; p++) u += __ldg(Z + 24 + 5 * p + k) * sWall[22 + p];
                oa[t] = 0.84515425472851657f * u * g;
            } else {
                int k = t - 9;
                float g = fsig(0.5f * (z0.x * sWall[6] + z0.y * sWall[9] + z0.z * sWall[12] + z0.w * sWall[15]) + sBall[3]);
                float u = 0.f;
#pragma unroll
                for (int p = 0; p < 6; p++) u += __ldg(Z + 60 + 7 * p + k) * sWall[29 + p];
                oa[t] = 1.08012344973464367f * u * g;   // sqrt(7/6)
            }
        }
    }
}

extern "C" void kernel_launch(void* const* d_in, const int* in_sizes, int n_in,
                              void* d_out, int out_size) {
    const float* x    = (const float*)d_in[0];
    const float* y    = (const float*)d_in[1];
    const float* wcg  = (const float*)d_in[2];
    const float* bcg  = (const float*)d_in[3];
    const float* wall = (const float*)d_in[4];
    const float* ball = (const float*)d_in[5];
    float* out = (float*)d_out;

    w3j_init_kernel<<<23, 256>>>();
    w3j_compress_kernel<<<1, 128>>>();
    z_pass_kernel<<<ZP_GRID, ZP_WARPS * 32>>>(x, y);
    cg_main_kernel<<<GRID, 128>>>(wcg, bcg, wall, ball, out);
}

// round 9
// speedup vs baseline: 1.5612x; 1.5612x over previous
#include <cuda_runtime.h>
#include <math.h>

#define EDGES 65536
#define GRID  2048
#define EPB   (EDGES / GRID)   // 32 edges per block
#define W3J_TOTAL 1875
#define NZ_MAX 1875
#define OUT_ALL_OFF ((size_t)EDGES * 9 * 128)   // 75497472
#define NSPLIT 29              // 128 - 99 spare thread tasks

// ---- key tables: (la, lb, lo) for the 23 distinct W3J tensors, in weight-path order ----
__constant__ int KEY_LA[23]  = {0,1,2,3, 0,1,1,2,2,3, 0,1,1,2,2,3,3, 0,1,2,2,3,3};
__constant__ int KEY_LB[23]  = {0,1,2,3, 1,0,2,1,3,2, 2,1,3,0,2,1,3, 3,2,1,3,0,2};
__constant__ int KEY_LO[23]  = {0,0,0,0, 1,1,1,1,1,1, 2,2,2,2,2,2,2, 3,3,3,3,3,3};
__constant__ int W3J_OFF[23] = {0,1,10,35, 84,93,102,147,192,297,
                                402,427,472,577,602,727,832,
                                1077,1126,1231,1336,1581,1630};

__constant__ float c_factf[11]  = {1.f,1.f,2.f,6.f,24.f,120.f,720.f,5040.f,40320.f,362880.f,3628800.f};
__constant__ float c_rfactf[11] = {1.0f, 1.0f, 0.5f, 1.0f/6.0f, 1.0f/24.0f, 1.0f/120.0f, 1.0f/720.0f,
                                   1.0f/5040.0f, 1.0f/40320.0f, 1.0f/362880.0f, 1.0f/3628800.0f};

__device__ float g_w3j[W3J_TOTAL];
__device__ float2 g_nz[NZ_MAX];
// per-thread task tables (built by compress kernel)
__device__ int g_toff[128];
__device__ int g_tcnt[128];
__device__ int g_tdst[128];    // z-index in padded layout, or -1
__device__ int g_tpair[128];   // 1 = add shfl-down(1) partner before writing
__device__ int g_total;

// ================= init: fp32 Wigner-3j tensors =================
struct F2 { float re, im; };
__device__ __forceinline__ F2 cmul(F2 a, F2 b) {
    return F2{a.re * b.re - a.im * b.im, a.re * b.im + a.im * b.re};
}
__device__ __forceinline__ F2 cconj(F2 a) { return F2{a.re, -a.im}; }
__device__ __forceinline__ F2 cscale(F2 a, float s) { return F2{a.re * s, a.im * s}; }

__device__ float su2_cg(int j1, int m1, int j2, int m2, int j3, int m3) {
    if (m3 != m1 + m2) return 0.0f;
    float pref = sqrtf((2.0f * j3 + 1.0f) * c_factf[j3 + j1 - j2] * c_factf[j3 - j1 + j2] *
                       c_factf[j1 + j2 - j3] * c_rfactf[j1 + j2 + j3 + 1]);
    pref *= sqrtf(c_factf[j3 + m3] * c_factf[j3 - m3] * c_factf[j1 - m1] * c_factf[j1 + m1] *
                  c_factf[j2 - m2] * c_factf[j2 + m2]);
    int kmin = max(0, max(j2 - j3 - m1, j1 - j3 + m2));
    int kmax = min(j1 + j2 - j3, min(j1 - m1, j2 + m2));
    float s = 0.0f;
    for (int k = kmin; k <= kmax; k++) {
        float term = c_rfactf[k] * c_rfactf[j1 + j2 - j3 - k] * c_rfactf[j1 - m1 - k] *
                     c_rfactf[j2 + m2 - k] * c_rfactf[j3 - j2 + m1 + k] * c_rfactf[j3 - j1 - m2 + k];
        s += (k & 1) ? -term : term;
    }
    return pref * s;
}

__device__ __forceinline__ F2 negi_pow(int l) {
    switch (l & 3) {
        case 0: return F2{1.0f, 0.0f};
        case 1: return F2{0.0f, -1.0f};
        case 2: return F2{-1.0f, 0.0f};
        default: return F2{0.0f, 1.0f};
    }
}

__device__ int q_col_entries(int l, int c, int* rows, F2* vals) {
    F2 pref = negi_pow(l);
    const float s = 0.70710678f;
    int mu = c - l;
    if (mu == 0) { rows[0] = l; vals[0] = pref; return 1; }
    if (mu > 0) {
        rows[0] = l - mu; vals[0] = cscale(pref, s);
        float sgn = (mu & 1) ? -1.0f : 1.0f;
        rows[1] = l + mu; vals[1] = cscale(pref, sgn * s);
        return 2;
    }
    int a = -mu;
    rows[0] = l - a; vals[0] = cmul(pref, F2{0.0f, -s});
    float sgn = (a & 1) ? -1.0f : 1.0f;
    rows[1] = l + a; vals[1] = cmul(pref, F2{0.0f, sgn * s});
    return 2;
}

__device__ int q_row_entries(int l, int r, int* cols, F2* vals) {
    F2 pref = negi_pow(l);
    const float s = 0.70710678f;
    int mu = r - l;
    if (mu == 0) { cols[0] = l; vals[0] = pref; return 1; }
    if (mu < 0) {
        int a = -mu;
        cols[0] = l + a; vals[0] = cscale(pref, s);
        cols[1] = l - a; vals[1] = cmul(pref, F2{0.0f, -s});
        return 2;
    }
    float sgn = (mu & 1) ? -1.0f : 1.0f;
    cols[0] = l + mu; vals[0] = cscale(pref, sgn * s);
    cols[1] = l - mu; vals[1] = cmul(pref, F2{0.0f, sgn * s});
    return 2;
}

__global__ void w3j_init_kernel() {
    __shared__ float sC[343];
    __shared__ float sCr[245];
    __shared__ float sred[256];
    int key = blockIdx.x;
    int la = KEY_LA[key], lb = KEY_LB[key], lo = KEY_LO[key];
    int na = 2 * la + 1, nb = 2 * lb + 1, no = 2 * lo + 1;
    int n = na * nb * no;
    int t = threadIdx.x;

    for (int idx = t; idx < n; idx += blockDim.x) {
        int i = idx / (nb * no);
        int rem = idx % (nb * no);
        int k = rem / no;
        int m = rem % no;
        int m1 = i - la, m2 = k - lb, m3 = m - lo;
        sC[idx] = (m3 == m1 + m2) ? su2_cg(la, m1, lb, m2, lo, m3) : 0.0f;
    }
    __syncthreads();

    float local_sq = 0.0f;
    for (int idx = t; idx < n; idx += blockDim.x) {
        int ja = idx / (nb * no);
        int rem = idx % (nb * no);
        int jb = rem / no;
        int jn = rem % no;
        int r1[2]; F2 v1[2]; int n1 = q_col_entries(la, ja, r1, v1);
        int r2[2]; F2 v2[2]; int n2 = q_col_entries(lb, jb, r2, v2);
        int c3[2]; F2 v3[2]; int n3 = q_row_entries(lo, jn, c3, v3);
        F2 acc{0.0f, 0.0f};
        for (int a = 0; a < n1; a++)
            for (int b = 0; b < n2; b++)
                for (int c = 0; c < n3; c++) {
                    F2 q = cmul(cmul(v1[a], v2[b]), cconj(v3[c]));
                    float cv = sC[(r1[a] * nb + r2[b]) * no + c3[c]];
                    acc.re += q.re * cv;
                    acc.im += q.im * cv;
                }
        sCr[idx] = acc.re;
        local_sq += acc.re * acc.re;
    }
    sred[t] = local_sq;
    __syncthreads();
    for (int s = 128; s > 0; s >>= 1) {
        if (t < s) sred[t] += sred[t + s];
        __syncthreads();
    }
    float inv = rsqrtf(sred[0]);
    for (int idx = t; idx < n; idx += blockDim.x)
        g_w3j[W3J_OFF[key] + idx] = sCr[idx] * inv;
}

// slot (0..98) -> (key, k-within-output)
__device__ __forceinline__ void slot_decode(int t, int& key, int& k) {
    if (t < 4) { key = t; k = 0; }
    else if (t < 22) { int q = t - 4; key = 4 + q / 3; k = q % 3; }
    else if (t < 57) { int q = t - 22; key = 10 + q / 5; k = q % 5; }
    else { int q = t - 57; key = 17 + q / 7; k = q % 7; }
}

// slot -> index within padded z layout (sZ[104])
__device__ __forceinline__ int zmap(int slot) {
    return slot + (slot >= 22 ? 2 : 0) + (slot >= 57 ? 1 : 0);
}

// ========== compress: nonzero lists + load-balanced 128-thread task table ==========
__global__ void w3j_compress_kernel() {
    __shared__ int scnt[99];
    __shared__ int soff[99];
    int t = threadIdx.x;
    int key = 0, k = 0;
    bool valid = (t < 99);
    if (valid) slot_decode(t, key, k);
    int la = KEY_LA[key], lb = KEY_LB[key], lo = KEY_LO[key];
    int na = 2 * la + 1, nb = 2 * lb + 1, no = 2 * lo + 1;
    int woff = W3J_OFF[key];
    int cnt = 0;
    if (valid) {
        for (int i = 0; i < na; i++)
            for (int j = 0; j < nb; j++)
                if (fabsf(g_w3j[woff + (i * nb + j) * no + k]) > 1e-10f) cnt++;
        scnt[t] = cnt;
    }
    __syncthreads();
    if (t == 0) {
        int acc = 0;
        for (int i = 0; i < 99; i++) { soff[i] = acc; acc += scnt[i]; }
        g_total = acc;
    }
    __syncthreads();
    if (valid) {
        int w = soff[t];
        for (int i = 0; i < na; i++)
            for (int j = 0; j < nb; j++) {
                float c = g_w3j[woff + (i * nb + j) * no + k];
                if (fabsf(c) > 1e-10f) {
                    int pidx = (la * la + i) * 16 + (lb * lb + j);  // index into 16x16 product table
                    g_nz[w++] = make_float2(c, __int_as_float(pidx));
                }
            }
    }
    __syncthreads();
    // rank slots by nnz (descending, ties by index); split top NSPLIT across thread pairs
    if (valid) {
        int rank = 0;
        for (int j = 0; j < 99; j++)
            if (scnt[j] > cnt || (scnt[j] == cnt && j < t)) rank++;
        int off = soff[t];
        int dst = zmap(t);
        if (rank < NSPLIT) {
            int p0 = 2 * rank;
            int c1 = (cnt + 1) >> 1;
            g_toff[p0] = off;          g_tcnt[p0] = c1;       g_tdst[p0] = dst;  g_tpair[p0] = 1;
            g_toff[p0 + 1] = off + c1; g_tcnt[p0 + 1] = cnt - c1; g_tdst[p0 + 1] = -1; g_tpair[p0 + 1] = 0;
        } else {
            int p = 2 * NSPLIT + (rank - NSPLIT);   // 58..127
            g_toff[p] = off; g_tcnt[p] = cnt; g_tdst[p] = dst; g_tpair[p] = 0;
        }
    }
}

// ================= main kernel =================
__device__ __forceinline__ float fsig(float v) { return 1.0f / (1.0f + __expf(-v)); }

__global__ void __launch_bounds__(128)
cg_main_kernel(const float* __restrict__ x, const float* __restrict__ y,
               const float* __restrict__ wcg, const float* __restrict__ bcg,
               const float* __restrict__ wall, const float* __restrict__ ball,
               float* __restrict__ out) {
    __shared__ float2 snz[NZ_MAX];
    __shared__ float sProd[4][256];                 // per-warp product tables
    __shared__ __align__(16) float sZ[2][104];      // ping-pong z buffers
    __shared__ float sWall[35];
    __shared__ float sBall[4];

    int t = threadIdx.x;
    int w = t >> 5, lane = t & 31;
    int total = g_total;
    for (int i = t; i < total; i += 128) snz[i] = g_nz[i];
    if (t < 35) sWall[t] = wall[t];
    if (t < 4) sBall[t] = ball[t];

    // per-thread phase-1 task
    int toff = g_toff[t], tcnt = g_tcnt[t], tdst = g_tdst[t], tpair = g_tpair[t];

    // per-channel weights hoisted to registers (fixed across edges)
    float w00 = wcg[t], w01 = wcg[128 + t], w02 = wcg[256 + t], w03 = wcg[384 + t];
    float a0w = wcg[512 + t], a1w = wcg[768 + t], a2w = wcg[1024 + t], a3w = wcg[1280 + t];
    float c0w = wcg[640 + t], c1w = wcg[896 + t], c2w = wcg[1152 + t], c3w = wcg[1408 + t];
    float uw0 = wcg[1536 + t], uw1 = wcg[1664 + t], uw2 = wcg[1792 + t];
    float uw3 = wcg[1920 + t], uw4 = wcg[2048 + t], uw5 = wcg[2176 + t];
    float vw0 = wcg[2304 + t], vw1 = wcg[2432 + t], vw2 = wcg[2560 + t], vw3 = wcg[2688 + t];
    float vw4 = wcg[2816 + t], vw5 = wcg[2944 + t], vw6 = wcg[3072 + t];
    float b0 = bcg[t], b1 = bcg[128 + t], b2 = bcg[256 + t];

    int e0 = blockIdx.x * EPB;
    // every warp holds the edge's x/y in lanes 0-31 (x in 0-15, y in 16-31)
    float pre = (lane < 16) ? x[(size_t)e0 * 16 + lane] : y[(size_t)e0 * 16 + (lane - 16)];

    // CRITICAL: order the cooperative snz/sWall/sBall loads before ANY thread's
    // phase-1 reads (this was the R8 illegal-access bug: garbage snz.y used as
    // a shared-memory index on the first edge).
    __syncthreads();

    for (int ei = 0; ei < EPB; ++ei) {
        int e = e0 + ei;
        // each warp builds its own 16x16 product table (no block barrier needed)
        float v = pre;
#pragma unroll
        for (int r = 0; r < 8; r++) {
            int p = r * 32 + lane;
            sProd[w][p] = __shfl_sync(0xffffffffu, v, p >> 4) *
                          __shfl_sync(0xffffffffu, v, 16 + (p & 15));
        }
        if (ei + 1 < EPB) {
            int en = e + 1;
            pre = (lane < 16) ? x[(size_t)en * 16 + lane] : y[(size_t)en * 16 + (lane - 16)];
        }
        __syncwarp();

        // ---- phase 1: balanced sparse z tasks, warp-local reads ----
        float* zb = sZ[ei & 1];
        {
            const float* P = sProd[w];
            float acc = 0.0f;
            for (int n = 0; n < tcnt; n++) {
                float2 ent = snz[toff + n];
                acc = fmaf(ent.x, P[__float_as_int(ent.y)], acc);
            }
            float oth = __shfl_down_sync(0xffffffffu, acc, 1);
            if (tpair) acc += oth;
            if (tdst >= 0) zb[tdst] = acc;
        }
        __syncthreads();   // the only per-edge block barrier

        // ---- phase 2: per-channel outputs (t = channel) ----
        const float* Z = zb;
        float4 z0 = *(const float4*)Z;
        float v0 = fmaf(z0.x, w00, fmaf(z0.y, w01, fmaf(z0.z, w02, z0.w * w03)));
        v0 = 0.5f * v0 + b0;
        float scv = v0 * fsig(v0);
        float g0 = fmaf(z0.x, a0w, fmaf(z0.y, a1w, fmaf(z0.z, a2w, z0.w * a3w)));
        g0 = fsig(0.5f * g0 + b1);
        float g1 = fmaf(z0.x, c0w, fmaf(z0.y, c1w, fmaf(z0.z, c2w, z0.w * c3w)));
        g1 = fsig(0.5f * g1 + b2);

        // entry 2 (lo=1): u_k = sum_p Z[4+3p+k]*uw_p (18 values at Z+4)
        float u0, u1, u2;
        {
            float4 v4;
            v4 = *(const float4*)(Z + 4);
            u0 = v4.x * uw0; u1 = v4.y * uw0; u2 = v4.z * uw0; u0 = fmaf(v4.w, uw1, u0);
            v4 = *(const float4*)(Z + 8);
            u1 = fmaf(v4.x, uw1, u1); u2 = fmaf(v4.y, uw1, u2);
            u0 = fmaf(v4.z, uw2, u0); u1 = fmaf(v4.w, uw2, u1);
            v4 = *(const float4*)(Z + 12);
            u2 = fmaf(v4.x, uw2, u2); u0 = fmaf(v4.y, uw3, u0);
            u1 = fmaf(v4.z, uw3, u1); u2 = fmaf(v4.w, uw3, u2);
            v4 = *(const float4*)(Z + 16);
            u0 = fmaf(v4.x, uw4, u0); u1 = fmaf(v4.y, uw4, u1);
            u2 = fmaf(v4.z, uw4, u2); u0 = fmaf(v4.w, uw5, u0);
            float2 v2 = *(const float2*)(Z + 20);
            u1 = fmaf(v2.x, uw5, u1); u2 = fmaf(v2.y, uw5, u2);
        }
        // entry 3 (lo=2): q_k = sum_p Z[24+5p+k]*vw_p (35 values at Z+24)
        float q0, q1, q2, q3, q4;
        {
            float4 v4;
            v4 = *(const float4*)(Z + 24);
            q0 = v4.x * vw0; q1 = v4.y * vw0; q2 = v4.z * vw0; q3 = v4.w * vw0;
            v4 = *(const float4*)(Z + 28);
            q4 = v4.x * vw0; q0 = fmaf(v4.y, vw1, q0); q1 = fmaf(v4.z, vw1, q1); q2 = fmaf(v4.w, vw1, q2);
            v4 = *(const float4*)(Z + 32);
            q3 = fmaf(v4.x, vw1, q3); q4 = fmaf(v4.y, vw1, q4); q0 = fmaf(v4.z, vw2, q0); q1 = fmaf(v4.w, vw2, q1);
            v4 = *(const float4*)(Z + 36);
            q2 = fmaf(v4.x, vw2, q2); q3 = fmaf(v4.y, vw2, q3); q4 = fmaf(v4.z, vw2, q4); q0 = fmaf(v4.w, vw3, q0);
            v4 = *(const float4*)(Z + 40);
            q1 = fmaf(v4.x, vw3, q1); q2 = fmaf(v4.y, vw3, q2); q3 = fmaf(v4.z, vw3, q3); q4 = fmaf(v4.w, vw3, q4);
            v4 = *(const float4*)(Z + 44);
            q0 = fmaf(v4.x, vw4, q0); q1 = fmaf(v4.y, vw4, q1); q2 = fmaf(v4.z, vw4, q2); q3 = fmaf(v4.w, vw4, q3);
            v4 = *(const float4*)(Z + 48);
            q4 = fmaf(v4.x, vw4, q4); q0 = fmaf(v4.y, vw5, q0); q1 = fmaf(v4.z, vw5, q1); q2 = fmaf(v4.w, vw5, q2);
            v4 = *(const float4*)(Z + 52);
            q3 = fmaf(v4.x, vw5, q3); q4 = fmaf(v4.y, vw5, q4); q0 = fmaf(v4.z, vw6, q0); q1 = fmaf(v4.w, vw6, q1);
            v4 = *(const float4*)(Z + 56);   // Z[59] is padding (lane discarded)
            q2 = fmaf(v4.x, vw6, q2); q3 = fmaf(v4.y, vw6, q3); q4 = fmaf(v4.z, vw6, q4);
        }

        const float S1 = 0.70710678118654752f;   // sqrt(3/6)
        const float S2 = 0.84515425472851657f;   // sqrt(5/7)
        size_t base = ((size_t)e * 9) * 128 + t;
        out[base] = scv;
        float gg = S1 * g0;
        out[base + 128] = u0 * gg;
        out[base + 256] = u1 * gg;
        out[base + 384] = u2 * gg;
        float hh = S2 * g1;
        out[base + 512] = q0 * hh;
        out[base + 640] = q1 * hh;
        out[base + 768] = q2 * hh;
        out[base + 896] = q3 * hh;
        out[base + 1024] = q4 * hh;

        // ---- "all" branch: 16 outputs ----
        if (t < 16) {
            float* oa = out + OUT_ALL_OFF + (size_t)e * 16;
            if (t == 0) {
                float vv = 0.5f * (z0.x * sWall[0] + z0.y * sWall[1] + z0.z * sWall[2] + z0.w * sWall[3]) + sBall[0];
                oa[0] = vv * fsig(vv);
            } else if (t < 4) {
                int k = t - 1;
                float g = fsig(0.5f * (z0.x * sWall[4] + z0.y * sWall[7] + z0.z * sWall[10] + z0.w * sWall[13]) + sBall[1]);
                float u = 0.f;
#pragma unroll
                for (int p = 0; p < 6; p++) u += Z[4 + 3 * p + k] * sWall[16 + p];
                oa[t] = 0.70710678118654752f * u * g;
            } else if (t < 9) {
                int k = t - 4;
                float g = fsig(0.5f * (z0.x * sWall[5] + z0.y * sWall[8] + z0.z * sWall[11] + z0.w * sWall[14]) + sBall[2]);
                float u = 0.f;
#pragma unroll
                for (int p = 0; p < 7; p++) u += Z[24 + 5 * p + k] * sWall[22 + p];
                oa[t] = 0.84515425472851657f * u * g;
            } else {
                int k = t - 9;
                float g = fsig(0.5f * (z0.x * sWall[6] + z0.y * sWall[9] + z0.z * sWall[12] + z0.w * sWall[15]) + sBall[3]);
                float u = 0.f;
#pragma unroll
                for (int p = 0; p < 6; p++) u += Z[60 + 7 * p + k] * sWall[29 + p];
                oa[t] = 1.08012344973464367f * u * g;   // sqrt(7/6)
            }
        }
        // no trailing barrier: ping-pong sZ + the per-edge barrier give the
        // needed ordering (writes to this buffer recur only 2 barriers later,
        // and reaching edge ei+2's phase 1 requires passing edge ei+1's barrier,
        // which every warp reaches only after its edge-ei phase-2 reads).
    }
}

extern "C" void kernel_launch(void* const* d_in, const int* in_sizes, int n_in,
                              void* d_out, int out_size) {
    const float* x    = (const float*)d_in[0];
    const float* y    = (const float*)d_in[1];
    const float* wcg  = (const float*)d_in[2];
    const float* bcg  = (const float*)d_in[3];
    const float* wall = (const float*)d_in[4];
    const float* ball = (const float*)d_in[5];
    float* out = (float*)d_out;

    w3j_init_kernel<<<23, 256>>>();
    w3j_compress_kernel<<<1, 128>>>();
    cg_main_kernel<<<GRID, 128>>>(x, y, wcg, bcg, wall, ball, out);
}